// round 13
// baseline (speedup 1.0000x reference)
#include <cuda_runtime.h>
#include <cstdint>

#define BN 64
#define PP 8732
#define CC 81
#define KT 16
#define NR (BN * PP)          // 558848
#define TR 128                // rows per CE tile
#define CEB 4366              // NR / 128 exactly
#define NCH 16
#define CHUNK 546
#define MBLK (BN * NCH)       // 1024 matchA blocks (first in grid)
#define TPB 256
#define THRESH 0.5f
#define VAR0 0.1f
#define VAR1 0.2f
#define TPK 1024
#define PPADK 9216            // 1024*9 uniform bound (phase-1 collective loop)
#define IMGB (PP * 4)         // 34928 bytes per per-image array (16B aligned)
#define NBIN 8192

// ---------------- scratch ----------------
__device__ __align__(16) float g_bto[NR];
__device__ __align__(16) int   g_bti[NR];
__device__ __align__(16) float g_lm[NR];
__device__ unsigned long long g_best[BN * KT];  // idempotent atomicMax accumulator
__device__ float g_loss_l[BN];
__device__ float g_loss_c[BN];
__device__ int   g_num_pos[BN];
__device__ int   g_done;                         // self-resetting

// ---------------- helpers ----------------
static __device__ __forceinline__ unsigned su32(const void* p) {
    return (unsigned)__cvta_generic_to_shared(p);
}
#define MBAR_INIT(a, c) \
    asm volatile("mbarrier.init.shared.b64 [%0], %1;" :: "r"(a), "r"(c) : "memory")
#define MBAR_EXPECT(a, n) \
    asm volatile("mbarrier.arrive.expect_tx.shared.b64 _, [%0], %1;" :: "r"(a), "r"(n) : "memory")
#define BULK_G2S(dst, src, n, mbar) \
    asm volatile("cp.async.bulk.shared::cta.global.mbarrier::complete_tx::bytes [%0], [%1], %2, [%3];" \
                 :: "r"(dst), "l"(src), "r"(n), "r"(mbar) : "memory")
#define MBAR_WAITP(a, par) do {                                                     \
    unsigned _dn = 0;                                                               \
    while (!_dn) {                                                                  \
        asm volatile("{\n\t.reg .pred p;\n\t"                                       \
            "mbarrier.try_wait.parity.acquire.cta.shared::cta.b64 p, [%1], %2, 0x989680;\n\t" \
            "selp.b32 %0, 1, 0, p;\n\t}"                                            \
            : "=r"(_dn) : "r"(a), "r"((unsigned)(par)) : "memory");                 \
    }                                                                               \
} while (0)

static __device__ __forceinline__ int warp_suffix_incl(int v, int lane) {
#pragma unroll
    for (int o = 1; o < 32; o <<= 1) {
        int t = __shfl_down_sync(0xFFFFFFFFu, v, o);
        if (lane + o < 32) v += t;
    }
    return v;
}

// ---------------- smem union for k_big ----------------
struct SmCE   { float buf[TR * CC]; float part[2][TR]; };                      // 42496 B
struct SmMatch{ float4 pr[CHUNK]; float4 tt[KT]; float area[KT]; unsigned long long best[KT]; };
union SmU { SmCE ce; SmMatch ma; };

// ---------------- kernel 1: matchA + CE (128-row TMA tiles, 256 thr, split-row) ----------------
__global__ __launch_bounds__(TPB) void k_big(const float* __restrict__ conf,
                                             const float* __restrict__ priors,
                                             const float* __restrict__ targets) {
    __shared__ __align__(16) SmU sm;
    __shared__ __align__(8) unsigned long long s_mbar;
    const int blk = blockIdx.x;
    const int tid = threadIdx.x;

    if (blk >= MBLK) {
        // ------- CE role: 256 threads, each does half a row -------
        const int tile = blk - MBLK;
        const int row0 = tile * TR;
        const unsigned mb = su32(&s_mbar);
        if (tid == 0) MBAR_INIT(mb, 1);
        __syncthreads();
        if (tid == 0) {
            MBAR_EXPECT(mb, (unsigned)(TR * CC * 4));
            BULK_G2S(su32(sm.ce.buf), conf + (size_t)row0 * CC, (unsigned)(TR * CC * 4), mb);
        }
        MBAR_WAITP(mb, 0);

        const int r = tid & (TR - 1);
        const int half = tid >> 7;
        const float* row = sm.ce.buf + r * CC;
        float s0 = 0.0f, s1 = 0.0f, s2 = 0.0f, s3 = 0.0f;
        if (half == 0) {
#pragma unroll
            for (int c = 0; c < 40; c += 4) {
                s0 += __expf(row[c]);
                s1 += __expf(row[c + 1]);
                s2 += __expf(row[c + 2]);
                s3 += __expf(row[c + 3]);
            }
        } else {
#pragma unroll
            for (int c = 40; c < 80; c += 4) {
                s0 += __expf(row[c]);
                s1 += __expf(row[c + 1]);
                s2 += __expf(row[c + 2]);
                s3 += __expf(row[c + 3]);
            }
            s0 += __expf(row[80]);
        }
        sm.ce.part[half][r] = (s0 + s1) + (s2 + s3);
        __syncthreads();
        if (tid < TR) {
            const float lse = __logf(sm.ce.part[0][tid] + sm.ce.part[1][tid]);
            g_lm[row0 + tid] = lse - sm.ce.buf[tid * CC];
        }
    } else {
        // ------- matchA role -------
        const int b = blk >> 4;
        const int c = blk & 15;

        if (tid < KT) {
            const float* tg = targets + (size_t)(b * KT + tid) * 6;
            sm.ma.tt[tid] = make_float4(tg[2], tg[3], tg[4], tg[5]);
            sm.ma.area[tid] = (tg[4] - tg[2]) * (tg[5] - tg[3]);
            sm.ma.best[tid] = 0ull;
        }
        const int p0 = c * CHUNK;
        const int np = (p0 + CHUNK <= PP) ? CHUNK : (PP - p0);
        for (int i = tid; i < np; i += TPB)
            sm.ma.pr[i] = ((const float4*)priors)[p0 + i];
        __syncthreads();

        for (int i = tid; i < np; i += TPB) {
            const float4 pr = sm.ma.pr[i];
            const float parea = (pr.z - pr.x) * (pr.w - pr.y);
            float bestov = -1.0f;
            int besti = 0;
#pragma unroll
            for (int k = 0; k < KT; k++) {
                const float4 t = sm.ma.tt[k];
                float ix = fminf(t.z, pr.z) - fmaxf(t.x, pr.x);
                float iy = fminf(t.w, pr.w) - fmaxf(t.y, pr.y);
                float inter = fmaxf(ix, 0.0f) * fmaxf(iy, 0.0f);
                float ov = inter / (sm.ma.area[k] + parea - inter);
                if (ov > bestov) { bestov = ov; besti = k; }
            }
            g_bto[b * PP + p0 + i] = bestov;
            g_bti[b * PP + p0 + i] = besti;
        }

        for (int k = 0; k < KT; k++) {
            const float4 t = sm.ma.tt[k];
            const float ta = sm.ma.area[k];
            unsigned long long key = 0ull;
            for (int i = tid; i < np; i += TPB) {
                const float4 pr = sm.ma.pr[i];
                const float parea = (pr.z - pr.x) * (pr.w - pr.y);
                float ix = fminf(t.z, pr.z) - fmaxf(t.x, pr.x);
                float iy = fminf(t.w, pr.w) - fmaxf(t.y, pr.y);
                float inter = fmaxf(ix, 0.0f) * fmaxf(iy, 0.0f);
                float ov = inter / (ta + parea - inter);
                unsigned long long kk =
                    ((unsigned long long)__float_as_uint(ov) << 32) |
                    (unsigned long long)(0xFFFFFFFFu - (unsigned)(p0 + i));
                if (kk > key) key = kk;
            }
#pragma unroll
            for (int o = 16; o; o >>= 1) {
                unsigned long long other = __shfl_xor_sync(0xFFFFFFFFu, key, o);
                if (other > key) key = other;
            }
            if ((tid & 31) == 0)
                atomicMax(&sm.ma.best[k], key);
        }
        __syncthreads();
        if (tid < KT)
            atomicMax(&g_best[b * KT + tid], sm.ma.best[tid]);
    }
}

// ---------------- kernel 2: smem-resident post with single-histogram select (R12) ----------------
extern __shared__ float psm[];

__global__ __launch_bounds__(TPK) void k_post(const float* __restrict__ conf,
                                              const float* __restrict__ loc,
                                              const float* __restrict__ priors,
                                              const float* __restrict__ targets,
                                              float* __restrict__ out) {
    const int b = blockIdx.x;
    const int tid = threadIdx.x;
    const int lane = tid & 31;
    const int w = tid >> 5;
    const int bPP = b * PP;

    float* s_bto  = psm;
    float* s_lm   = psm + PP;
    int*   s_bti  = (int*)(psm + 2 * PP);
    int*   s_hist = (int*)(psm + 3 * PP);
    float* s_list1 = s_bto;
    float* s_list2 = (float*)s_bti;

    __shared__ int s_wtot[32], s_wsuf[32];
    __shared__ float4 s_tt[KT];
    __shared__ int s_lab[KT];
    __shared__ float s_rf[32], s_rs[32];
    __shared__ int s_ri[32];
    __shared__ float s_spos_sh, s_lsum_sh, s_T;
    __shared__ int s_npos_sh, s_last;
    __shared__ int s_B, s_rem, s_B2, s_rem2, s_B3, s_rem3;
    __shared__ int s_cnt1, s_cnt2;
    __shared__ __align__(8) unsigned long long s_mbar;

    const unsigned mb = su32(&s_mbar);
    if (tid == 0) {
        MBAR_INIT(mb, 1);
        MBAR_EXPECT(mb, 3u * IMGB);
        BULK_G2S(su32(s_bto), g_bto + bPP, (unsigned)IMGB, mb);
        BULK_G2S(su32(s_lm),  g_lm  + bPP, (unsigned)IMGB, mb);
        BULK_G2S(su32(s_bti), g_bti + bPP, (unsigned)IMGB, mb);
        s_T = 0.0f; s_cnt1 = 0; s_cnt2 = 0;
    }
    if (tid < KT) {
        const float* tg = targets + (size_t)(b * KT + tid) * 6;
        s_lab[tid] = (int)tg[1];
        s_tt[tid] = make_float4(tg[2], tg[3], tg[4], tg[5]);
    }
#pragma unroll
    for (int i = 0; i < NBIN / TPK; i++)
        s_hist[tid + i * TPK] = 0;
    __syncthreads();
    MBAR_WAITP(mb, 0);

    if (tid == 0) {
        for (int k = 0; k < KT; k++) {
            unsigned long long key = g_best[b * KT + k];
            const int p = (int)(0xFFFFFFFFu - (unsigned)(key & 0xFFFFFFFFull));
            s_bto[p] = __uint_as_float((unsigned)(key >> 32));
            s_bti[p] = k;
        }
    }
    __syncthreads();

    float lsum = 0.0f, spos = 0.0f;
    int cnt = 0;
    for (int p = tid; p < PPADK; p += TPK) {
        const bool valid = p < PP;
        float lmv = 0.0f;
        if (valid) {
            const float ov = s_bto[p];
            const int ki = s_bti[p];
            const int ct = (ov < THRESH) ? 0 : s_lab[ki];
            lmv = s_lm[p];
            if (ct > 0) {
                cnt++;
                const float* crow = conf + (size_t)(bPP + p) * CC;
                spos += lmv + crow[0] - crow[ct];
                lmv = 0.0f;
                s_lm[p] = 0.0f;
                const float4 pr = ((const float4*)priors)[p];
                const float pcx = 0.5f * (pr.x + pr.z), pcy = 0.5f * (pr.y + pr.w);
                const float pw = pr.z - pr.x, ph = pr.w - pr.y;
                const float4 t = s_tt[ki];
                float g0 = (0.5f * (t.x + t.z) - pcx) / (VAR0 * pw);
                float g1 = (0.5f * (t.y + t.w) - pcy) / (VAR0 * ph);
                float g2 = logf((t.z - t.x) / pw) / VAR1;
                float g3 = logf((t.w - t.y) / ph) / VAR1;
                const float4 ld = ((const float4*)loc)[bPP + p];
                float d, ad;
                d = ld.x - g0; ad = fabsf(d); lsum += (ad < 1.0f) ? 0.5f * d * d : ad - 0.5f;
                d = ld.y - g1; ad = fabsf(d); lsum += (ad < 1.0f) ? 0.5f * d * d : ad - 0.5f;
                d = ld.z - g2; ad = fabsf(d); lsum += (ad < 1.0f) ? 0.5f * d * d : ad - 0.5f;
                d = ld.w - g3; ad = fabsf(d); lsum += (ad < 1.0f) ? 0.5f * d * d : ad - 0.5f;
            }
        }
        const int bin = (int)(__float_as_uint(lmv) >> 19);
        unsigned m = __match_any_sync(0xFFFFFFFFu, bin) &
                     __ballot_sync(0xFFFFFFFFu, valid);
        if (valid && lane == (__ffs(m) - 1))
            atomicAdd(&s_hist[bin], __popc(m));
    }
#pragma unroll
    for (int o = 16; o; o >>= 1) {
        lsum += __shfl_xor_sync(0xFFFFFFFFu, lsum, o);
        spos += __shfl_xor_sync(0xFFFFFFFFu, spos, o);
        cnt  += __shfl_xor_sync(0xFFFFFFFFu, cnt, o);
    }
    if (lane == 0) { s_rf[w] = lsum; s_rs[w] = spos; s_ri[w] = cnt; }
    __syncthreads();
    if (tid < 32) {
        float L = s_rf[tid], S = s_rs[tid];
        int C = s_ri[tid];
#pragma unroll
        for (int o = 16; o; o >>= 1) {
            L += __shfl_xor_sync(0xFFFFFFFFu, L, o);
            S += __shfl_xor_sync(0xFFFFFFFFu, S, o);
            C += __shfl_xor_sync(0xFFFFFFFFu, C, o);
        }
        if (tid == 0) { s_lsum_sh = L; s_spos_sh = S; s_npos_sh = C; }
    }
    __syncthreads();

    const int npos = s_npos_sh;
    int k = 3 * npos;
    if (k > PP - 1) k = PP - 1;

    if (k > 0) {
        int h[8];
        int tot = 0;
        const int base = tid * 8;
#pragma unroll
        for (int j = 0; j < 8; j++) { h[j] = s_hist[base + j]; tot += h[j]; }
        int sv = warp_suffix_incl(tot, lane);
        if (lane == 0) s_wtot[w] = sv;
        __syncthreads();
        if (tid < 32) {
            int t2 = warp_suffix_incl(s_wtot[tid], tid);
            s_wsuf[tid] = t2 - s_wtot[tid];
        }
        __syncthreads();
        int cumAbove = (sv - tot) + s_wsuf[w];
#pragma unroll
        for (int j = 7; j >= 0; j--) {
            const int c = cumAbove + h[j];
            if (c >= k && cumAbove < k) { s_B = base + j; s_rem = k - cumAbove; }
            cumAbove = c;
        }
        __syncthreads();
        const int B = s_B;

        float sum3 = 0.0f;
        for (int p = tid; p < PP; p += TPK) {
            const float lmv = s_lm[p];
            const int bin = (int)(__float_as_uint(lmv) >> 19);
            if (bin > B) sum3 += lmv;
            else if (bin == B) s_list1[atomicAdd(&s_cnt1, 1)] = lmv;
        }
#pragma unroll
        for (int o = 16; o; o >>= 1)
            sum3 += __shfl_xor_sync(0xFFFFFFFFu, sum3, o);
        if (lane == 0) atomicAdd(&s_T, sum3);

        if (tid < 1024) s_hist[tid] = 0;
        __syncthreads();
        const int cnt1 = s_cnt1;
        for (int i = tid; i < cnt1; i += TPK)
            atomicAdd(&s_hist[(__float_as_uint(s_list1[i]) >> 9) & 0x3FF], 1);
        __syncthreads();
        {
            const int totA = s_hist[tid & 1023] * (tid < 1024 ? 1 : 0);
            int svA = warp_suffix_incl(totA, lane);
            if (lane == 0) s_wtot[w] = svA;
            __syncthreads();
            if (tid < 32) {
                int t2 = warp_suffix_incl(s_wtot[tid], tid);
                s_wsuf[tid] = t2 - s_wtot[tid];
            }
            __syncthreads();
            const int cumE = (svA - totA) + s_wsuf[w];
            if (tid < 1024 && cumE + totA >= s_rem && cumE < s_rem) {
                s_B2 = tid;
                s_rem2 = s_rem - cumE;
            }
        }
        __syncthreads();
        const int B2 = s_B2;
        float sumA = 0.0f;
        for (int i = tid; i < cnt1; i += TPK) {
            const float v = s_list1[i];
            const int binA = (int)((__float_as_uint(v) >> 9) & 0x3FF);
            if (binA > B2) sumA += v;
            else if (binA == B2) s_list2[atomicAdd(&s_cnt2, 1)] = v;
        }
#pragma unroll
        for (int o = 16; o; o >>= 1)
            sumA += __shfl_xor_sync(0xFFFFFFFFu, sumA, o);
        if (lane == 0 && sumA != 0.0f) atomicAdd(&s_T, sumA);

        if (tid < 512) s_hist[tid] = 0;
        __syncthreads();
        const int cnt2 = s_cnt2;
        for (int i = tid; i < cnt2; i += TPK)
            atomicAdd(&s_hist[__float_as_uint(s_list2[i]) & 0x1FF], 1);
        __syncthreads();
        {
            const int totB = (tid < 512) ? s_hist[tid] : 0;
            int svB = warp_suffix_incl(totB, lane);
            if (lane == 0) s_wtot[w] = svB;
            __syncthreads();
            if (tid < 32) {
                int t2 = warp_suffix_incl(s_wtot[tid], tid);
                s_wsuf[tid] = t2 - s_wtot[tid];
            }
            __syncthreads();
            const int cumE = (svB - totB) + s_wsuf[w];
            if (tid < 512 && cumE + totB >= s_rem2 && cumE < s_rem2) {
                s_B3 = tid;
                s_rem3 = s_rem2 - cumE;
            }
        }
        __syncthreads();
        const int B3 = s_B3;
        float sumB = 0.0f;
        for (int i = tid; i < cnt2; i += TPK) {
            const float v = s_list2[i];
            if ((int)(__float_as_uint(v) & 0x1FF) > B3) sumB += v;
        }
#pragma unroll
        for (int o = 16; o; o >>= 1)
            sumB += __shfl_xor_sync(0xFFFFFFFFu, sumB, o);
        if (lane == 0 && sumB != 0.0f) atomicAdd(&s_T, sumB);
        if (tid == 0) {
            const unsigned bits = ((unsigned)B << 19) | ((unsigned)B2 << 9) | (unsigned)B3;
            s_T += (float)s_rem3 * __uint_as_float(bits);
        }
        __syncthreads();
    }

    if (tid == 0) {
        g_loss_l[b] = s_lsum_sh;
        g_loss_c[b] = s_spos_sh + s_T;
        g_num_pos[b] = npos;
        __threadfence();
        s_last = (atomicAdd(&g_done, 1) == BN - 1) ? 1 : 0;
    }
    __syncthreads();
    if (s_last) {
        if (tid < 64) {
            float lv = __ldcg(&g_loss_l[tid]);
            float cv = __ldcg(&g_loss_c[tid]);
            float nv = (float)__ldcg(&g_num_pos[tid]);
#pragma unroll
            for (int o = 16; o; o >>= 1) {
                lv += __shfl_xor_sync(0xFFFFFFFFu, lv, o);
                cv += __shfl_xor_sync(0xFFFFFFFFu, cv, o);
                nv += __shfl_xor_sync(0xFFFFFFFFu, nv, o);
            }
            if (lane == 0) { s_rf[w] = lv; s_rf[w + 2] = cv; s_rf[w + 4] = nv; }
        }
        __syncthreads();
        if (tid == 0) {
            const float n = fmaxf(s_rf[4] + s_rf[5], 1.0f);
            out[0] = (s_rf[0] + s_rf[1]) / n;
            out[1] = (s_rf[2] + s_rf[3]) / n;
            g_done = 0;   // self-reset
        }
    }
}

extern "C" void kernel_launch(void* const* d_in, const int* in_sizes, int n_in,
                              void* d_out, int out_size) {
    const float* loc = (const float*)d_in[0];
    const float* conf = (const float*)d_in[1];
    const float* priors = (const float*)d_in[2];
    const float* targets = (const float*)d_in[3];
    float* out = (float*)d_out;

    const int post_dyn = 3 * IMGB + NBIN * 4;   // 137552 B
    cudaFuncSetAttribute(k_post, cudaFuncAttributeMaxDynamicSharedMemorySize, post_dyn);

    k_big<<<MBLK + CEB, TPB>>>(conf, priors, targets);
    k_post<<<BN, TPK, post_dyn>>>(conf, loc, priors, targets, out);
}

// round 14
// speedup vs baseline: 1.2080x; 1.2080x over previous
#include <cuda_runtime.h>
#include <cstdint>

#define BN 64
#define PP 8732
#define CC 81
#define KT 16
#define NR (BN * PP)
#define TPI 69                 // tiles per image (68 full + 1 of 28 rows)
#define CEB (BN * TPI)         // 4416
#define NCH 16
#define CHUNK 546
#define MBLK (BN * NCH)        // 1024 matchA blocks (first in grid)
#define TPB 128
#define THRESH 0.5f
#define VAR0 0.1f
#define VAR1 0.2f
#define TPK 1024
#define IMGB (PP * 4)
#define NBIN 8192
#define L1CAP 2048
#define L2CAP 512

// ---------------- scratch ----------------
__device__ __align__(16) float g_bto[NR];
__device__ __align__(16) int   g_bti[NR];
__device__ __align__(16) float g_lm[NR];
__device__ int   g_hist[BN * NBIN];              // reset by k_post after use
__device__ unsigned long long g_best[BN * KT];   // idempotent atomicMax accumulator
__device__ float g_acc_l[BN], g_acc_s[BN];       // reset by k_post
__device__ int   g_acc_n[BN];                    // reset by k_post
__device__ int   g_match[BN];                    // reset by k_post
__device__ float g_loss_l[BN], g_loss_c[BN];
__device__ int   g_fn[BN];
__device__ int   g_done;                          // self-resetting

// ---------------- helpers ----------------
static __device__ __forceinline__ unsigned su32(const void* p) {
    return (unsigned)__cvta_generic_to_shared(p);
}
#define MBAR_INIT(a, c) \
    asm volatile("mbarrier.init.shared.b64 [%0], %1;" :: "r"(a), "r"(c) : "memory")
#define MBAR_EXPECT(a, n) \
    asm volatile("mbarrier.arrive.expect_tx.shared.b64 _, [%0], %1;" :: "r"(a), "r"(n) : "memory")
#define BULK_G2S(dst, src, n, mbar) \
    asm volatile("cp.async.bulk.shared::cta.global.mbarrier::complete_tx::bytes [%0], [%1], %2, [%3];" \
                 :: "r"(dst), "l"(src), "r"(n), "r"(mbar) : "memory")
#define MBAR_WAITP(a, par) do {                                                     \
    unsigned _dn = 0;                                                               \
    while (!_dn) {                                                                  \
        asm volatile("{\n\t.reg .pred p;\n\t"                                       \
            "mbarrier.try_wait.parity.acquire.cta.shared::cta.b64 p, [%1], %2, 0x989680;\n\t" \
            "selp.b32 %0, 1, 0, p;\n\t}"                                            \
            : "=r"(_dn) : "r"(a), "r"((unsigned)(par)) : "memory");                 \
    }                                                                               \
} while (0)

static __device__ __forceinline__ int warp_suffix_incl(int v, int lane) {
#pragma unroll
    for (int o = 1; o < 32; o <<= 1) {
        int t = __shfl_down_sync(0xFFFFFFFFu, v, o);
        if (lane + o < 32) v += t;
    }
    return v;
}

// ---------------- smem union for k_big ----------------
struct SmCE {
    float buf[TPI == 69 ? (128 * CC) : 0];   // 41472 B
    float4 tt[KT];
    int   lab[KT];
    int   fp[KT];
    float fov[KT];
    float rf[4], rs[4];
    int   ri[4];
};
struct SmMatch { float4 pr[CHUNK]; float4 tt[KT]; float area[KT]; unsigned long long best[KT]; };
union SmU { SmCE ce; SmMatch ma; };

// ---------------- kernel 1: matchA + fused CE/phase-1 ----------------
__global__ __launch_bounds__(TPB) void k_big(const float* __restrict__ conf,
                                             const float* __restrict__ loc,
                                             const float* __restrict__ priors,
                                             const float* __restrict__ targets) {
    __shared__ __align__(16) SmU sm;
    __shared__ __align__(8) unsigned long long s_mbar;
    const int blk = blockIdx.x;
    const int tid = threadIdx.x;
    const int lane = tid & 31;

    if (blk < MBLK) {
        // ================= matchA role =================
        const int b = blk >> 4;
        const int c = blk & 15;

        if (tid < KT) {
            const float* tg = targets + (size_t)(b * KT + tid) * 6;
            sm.ma.tt[tid] = make_float4(tg[2], tg[3], tg[4], tg[5]);
            sm.ma.area[tid] = (tg[4] - tg[2]) * (tg[5] - tg[3]);
            sm.ma.best[tid] = 0ull;
        }
        const int p0 = c * CHUNK;
        const int np = (p0 + CHUNK <= PP) ? CHUNK : (PP - p0);
        for (int i = tid; i < np; i += TPB)
            sm.ma.pr[i] = ((const float4*)priors)[p0 + i];
        __syncthreads();

        for (int i = tid; i < np; i += TPB) {
            const float4 pr = sm.ma.pr[i];
            const float parea = (pr.z - pr.x) * (pr.w - pr.y);
            float bestov = -1.0f;
            int besti = 0;
#pragma unroll
            for (int k = 0; k < KT; k++) {
                const float4 t = sm.ma.tt[k];
                float ix = fminf(t.z, pr.z) - fmaxf(t.x, pr.x);
                float iy = fminf(t.w, pr.w) - fmaxf(t.y, pr.y);
                float inter = fmaxf(ix, 0.0f) * fmaxf(iy, 0.0f);
                float ov = inter / (sm.ma.area[k] + parea - inter);
                if (ov > bestov) { bestov = ov; besti = k; }
            }
            g_bto[b * PP + p0 + i] = bestov;
            g_bti[b * PP + p0 + i] = besti;
        }

        for (int k = 0; k < KT; k++) {
            const float4 t = sm.ma.tt[k];
            const float ta = sm.ma.area[k];
            unsigned long long key = 0ull;
            for (int i = tid; i < np; i += TPB) {
                const float4 pr = sm.ma.pr[i];
                const float parea = (pr.z - pr.x) * (pr.w - pr.y);
                float ix = fminf(t.z, pr.z) - fmaxf(t.x, pr.x);
                float iy = fminf(t.w, pr.w) - fmaxf(t.y, pr.y);
                float inter = fmaxf(ix, 0.0f) * fmaxf(iy, 0.0f);
                float ov = inter / (ta + parea - inter);
                unsigned long long kk =
                    ((unsigned long long)__float_as_uint(ov) << 32) |
                    (unsigned long long)(0xFFFFFFFFu - (unsigned)(p0 + i));
                if (kk > key) key = kk;
            }
#pragma unroll
            for (int o = 16; o; o >>= 1) {
                unsigned long long other = __shfl_xor_sync(0xFFFFFFFFu, key, o);
                if (other > key) key = other;
            }
            if (lane == 0)
                atomicMax(&sm.ma.best[k], key);
        }
        __syncthreads();
        if (tid < KT)
            atomicMax(&g_best[b * KT + tid], sm.ma.best[tid]);
        __syncthreads();
        if (tid == 0) {
            __threadfence();
            atomicAdd(&g_match[b], 1);          // publish chunk done
        }
    } else {
        // ================= CE + phase-1 role (one image per block) =================
        const int t = blk - MBLK;
        const int b = t / TPI;
        const int ti = t - b * TPI;
        const int r0 = ti * 128;
        const int nv = (r0 + 128 <= PP) ? 128 : (PP - r0);
        const int bPP = b * PP;

        const unsigned mb = su32(&s_mbar);
        if (tid == 0) MBAR_INIT(mb, 1);
        __syncthreads();
        if (tid == 0) {
            MBAR_EXPECT(mb, (unsigned)(nv * CC * 4));
            BULK_G2S(su32(sm.ce.buf), conf + ((size_t)bPP + r0) * CC, (unsigned)(nv * CC * 4), mb);
            // wait for this image's matching to be complete
            while (*(volatile int*)&g_match[b] < NCH) __nanosleep(128);
            __threadfence();
        }
        __syncthreads();
        if (tid < KT) {
            const float* tg = targets + (size_t)(b * KT + tid) * 6;
            sm.ce.lab[tid] = (int)tg[1];
            sm.ce.tt[tid] = make_float4(tg[2], tg[3], tg[4], tg[5]);
            unsigned long long key = g_best[b * KT + tid];
            sm.ce.fp[tid] = (int)(0xFFFFFFFFu - (unsigned)(key & 0xFFFFFFFFull));
            sm.ce.fov[tid] = __uint_as_float((unsigned)(key >> 32));
        }
        __syncthreads();

        // independent global reads before the TMA wait
        const int p = r0 + tid;
        float ov = 0.0f;
        int ki = 0;
        if (tid < nv) {
            ov = g_bto[bPP + p];
            ki = g_bti[bPP + p];
#pragma unroll
            for (int k = 0; k < KT; k++)        // force-assign, last k wins
                if (p == sm.ce.fp[k]) { ov = sm.ce.fov[k]; ki = k; }
        }
        MBAR_WAITP(mb, 0);

        float lmv = 0.0f, spos = 0.0f, lsum = 0.0f;
        int cnt = 0;
        if (tid < nv) {
            const float* row = sm.ce.buf + tid * CC;
            float s0 = 0.0f, s1 = 0.0f, s2 = 0.0f, s3 = 0.0f;
#pragma unroll 5
            for (int i = 0; i + 3 < CC; i += 4) {
                s0 += __expf(row[i]);
                s1 += __expf(row[i + 1]);
                s2 += __expf(row[i + 2]);
                s3 += __expf(row[i + 3]);
            }
            s0 += __expf(row[CC - 1]);
            const float lse = __logf((s0 + s1) + (s2 + s3));
            lmv = lse - row[0];
            const int ct = (ov < THRESH) ? 0 : sm.ce.lab[ki];
            if (ct > 0) {
                cnt = 1;
                spos = lse - row[ct];
                lmv = 0.0f;
                const float4 pr = ((const float4*)priors)[p];
                const float pcx = 0.5f * (pr.x + pr.z), pcy = 0.5f * (pr.y + pr.w);
                const float pw = pr.z - pr.x, ph = pr.w - pr.y;
                const float4 tt = sm.ce.tt[ki];
                float g0 = (0.5f * (tt.x + tt.z) - pcx) / (VAR0 * pw);
                float g1 = (0.5f * (tt.y + tt.w) - pcy) / (VAR0 * ph);
                float g2 = __logf((tt.z - tt.x) / pw) / VAR1;
                float g3 = __logf((tt.w - tt.y) / ph) / VAR1;
                const float4 ld = ((const float4*)loc)[bPP + p];
                float d, ad;
                d = ld.x - g0; ad = fabsf(d); lsum += (ad < 1.0f) ? 0.5f * d * d : ad - 0.5f;
                d = ld.y - g1; ad = fabsf(d); lsum += (ad < 1.0f) ? 0.5f * d * d : ad - 0.5f;
                d = ld.z - g2; ad = fabsf(d); lsum += (ad < 1.0f) ? 0.5f * d * d : ad - 0.5f;
                d = ld.w - g3; ad = fabsf(d); lsum += (ad < 1.0f) ? 0.5f * d * d : ad - 0.5f;
            }
            g_lm[bPP + p] = lmv;
        }

        // warp-aggregated global histogram of lm (positives binned as 0)
        const bool valid = tid < nv;
        const int bin = (int)(__float_as_uint(lmv) >> 19);
        unsigned m = __match_any_sync(0xFFFFFFFFu, bin) &
                     __ballot_sync(0xFFFFFFFFu, valid);
        if (valid && lane == (__ffs(m) - 1))
            atomicAdd(&g_hist[b * NBIN + bin], __popc(m));

        // per-warp accumulate into per-image accumulators
#pragma unroll
        for (int o = 16; o; o >>= 1) {
            spos += __shfl_xor_sync(0xFFFFFFFFu, spos, o);
            lsum += __shfl_xor_sync(0xFFFFFFFFu, lsum, o);
            cnt  += __shfl_xor_sync(0xFFFFFFFFu, cnt, o);
        }
        if (lane == 0 && (tid & ~31) < nv) {
            if (cnt) {
                atomicAdd(&g_acc_n[b], cnt);
                atomicAdd(&g_acc_s[b], spos);
                atomicAdd(&g_acc_l[b], lsum);
            }
        }
    }
}

// ---------------- kernel 2: select + finalize (light) ----------------
// dyn smem: s_lm[PP] | s_list1[L1CAP] | s_list2[L2CAP]
extern __shared__ float psm[];

__global__ __launch_bounds__(TPK) void k_post(float* __restrict__ out) {
    const int b = blockIdx.x;
    const int tid = threadIdx.x;
    const int lane = tid & 31;
    const int w = tid >> 5;

    float* s_lm = psm;
    float* s_list1 = psm + PP;
    float* s_list2 = psm + PP + L1CAP;

    __shared__ int s_wtot[32], s_wsuf[32];
    __shared__ int s_h2[1024];
    __shared__ float s_rf[32];
    __shared__ int s_ri[32];
    __shared__ float s_T;
    __shared__ int s_B, s_rem, s_B2, s_rem2, s_B3, s_rem3;
    __shared__ int s_cnt1, s_cnt2, s_last;
    __shared__ __align__(8) unsigned long long s_mbar;

    const unsigned mb = su32(&s_mbar);
    if (tid == 0) {
        MBAR_INIT(mb, 1);
        MBAR_EXPECT(mb, (unsigned)IMGB);
        BULK_G2S(su32(s_lm), g_lm + b * PP, (unsigned)IMGB, mb);
        s_T = 0.0f; s_cnt1 = 0; s_cnt2 = 0;
    }
    __syncthreads();

    // read per-image accumulators, then reset them
    const int npos = g_acc_n[b];
    const float spos = g_acc_s[b];
    const float lsum = g_acc_l[b];
    if (tid == 0) {
        g_acc_n[b] = 0; g_acc_s[b] = 0.0f; g_acc_l[b] = 0.0f; g_match[b] = 0;
    }

    int k = 3 * npos;
    if (k > PP - 1) k = PP - 1;

    // load + zero this image's histogram, suffix scan to find boundary bin
    int h[8];
    int tot = 0;
    const int base = tid * 8;
    const int hb = b * NBIN;
#pragma unroll
    for (int j = 0; j < 8; j++) {
        h[j] = g_hist[hb + base + j];
        g_hist[hb + base + j] = 0;
        tot += h[j];
    }

    if (k > 0) {
        int sv = warp_suffix_incl(tot, lane);
        if (lane == 0) s_wtot[w] = sv;
        __syncthreads();
        if (tid < 32) {
            int t2 = warp_suffix_incl(s_wtot[tid], tid);
            s_wsuf[tid] = t2 - s_wtot[tid];
        }
        __syncthreads();
        int cumAbove = (sv - tot) + s_wsuf[w];
#pragma unroll
        for (int j = 7; j >= 0; j--) {
            const int c = cumAbove + h[j];
            if (c >= k && cumAbove < k) { s_B = base + j; s_rem = k - cumAbove; }
            cumAbove = c;
        }
        __syncthreads();
        const int B = s_B;

        MBAR_WAITP(mb, 0);

        // pass: sum above B, compact boundary bin
        float sum3 = 0.0f;
        for (int p = tid; p < PP; p += TPK) {
            const float lmv = s_lm[p];
            const int bin = (int)(__float_as_uint(lmv) >> 19);
            if (bin > B) sum3 += lmv;
            else if (bin == B) {
                const int idx = atomicAdd(&s_cnt1, 1);
                if (idx < L1CAP) s_list1[idx] = lmv;
            }
        }
#pragma unroll
        for (int o = 16; o; o >>= 1)
            sum3 += __shfl_xor_sync(0xFFFFFFFFu, sum3, o);
        if (lane == 0) atomicAdd(&s_T, sum3);

        // level A: 10-bit select within list1
        if (tid < 1024) s_h2[tid] = 0;
        __syncthreads();
        const int cnt1 = (s_cnt1 < L1CAP) ? s_cnt1 : L1CAP;
        for (int i = tid; i < cnt1; i += TPK)
            atomicAdd(&s_h2[(__float_as_uint(s_list1[i]) >> 9) & 0x3FF], 1);
        __syncthreads();
        {
            const int totA = s_h2[tid];
            int svA = warp_suffix_incl(totA, lane);
            if (lane == 0) s_wtot[w] = svA;
            __syncthreads();
            if (tid < 32) {
                int t2 = warp_suffix_incl(s_wtot[tid], tid);
                s_wsuf[tid] = t2 - s_wtot[tid];
            }
            __syncthreads();
            const int cumE = (svA - totA) + s_wsuf[w];
            if (cumE + totA >= s_rem && cumE < s_rem) {
                s_B2 = tid;
                s_rem2 = s_rem - cumE;
            }
        }
        __syncthreads();
        const int B2 = s_B2;
        float sumA = 0.0f;
        for (int i = tid; i < cnt1; i += TPK) {
            const float v = s_list1[i];
            const int binA = (int)((__float_as_uint(v) >> 9) & 0x3FF);
            if (binA > B2) sumA += v;
            else if (binA == B2) {
                const int idx = atomicAdd(&s_cnt2, 1);
                if (idx < L2CAP) s_list2[idx] = v;
            }
        }
#pragma unroll
        for (int o = 16; o; o >>= 1)
            sumA += __shfl_xor_sync(0xFFFFFFFFu, sumA, o);
        if (lane == 0 && sumA != 0.0f) atomicAdd(&s_T, sumA);

        // level B: 9-bit select within list2
        if (tid < 512) s_h2[tid] = 0;
        __syncthreads();
        const int cnt2 = (s_cnt2 < L2CAP) ? s_cnt2 : L2CAP;
        for (int i = tid; i < cnt2; i += TPK)
            atomicAdd(&s_h2[__float_as_uint(s_list2[i]) & 0x1FF], 1);
        __syncthreads();
        {
            const int totB = (tid < 512) ? s_h2[tid] : 0;
            int svB = warp_suffix_incl(totB, lane);
            if (lane == 0) s_wtot[w] = svB;
            __syncthreads();
            if (tid < 32) {
                int t2 = warp_suffix_incl(s_wtot[tid], tid);
                s_wsuf[tid] = t2 - s_wtot[tid];
            }
            __syncthreads();
            const int cumE = (svB - totB) + s_wsuf[w];
            if (tid < 512 && cumE + totB >= s_rem2 && cumE < s_rem2) {
                s_B3 = tid;
                s_rem3 = s_rem2 - cumE;
            }
        }
        __syncthreads();
        const int B3 = s_B3;
        float sumB = 0.0f;
        for (int i = tid; i < cnt2; i += TPK) {
            const float v = s_list2[i];
            if ((int)(__float_as_uint(v) & 0x1FF) > B3) sumB += v;
        }
#pragma unroll
        for (int o = 16; o; o >>= 1)
            sumB += __shfl_xor_sync(0xFFFFFFFFu, sumB, o);
        if (lane == 0 && sumB != 0.0f) atomicAdd(&s_T, sumB);
        if (tid == 0) {
            const unsigned bits = ((unsigned)B << 19) | ((unsigned)B2 << 9) | (unsigned)B3;
            s_T += (float)s_rem3 * __uint_as_float(bits);
        }
    } else {
        MBAR_WAITP(mb, 0);   // always drain the TMA before exit
    }
    __syncthreads();

    if (tid == 0) {
        g_loss_l[b] = lsum;
        g_loss_c[b] = spos + s_T;
        g_fn[b] = npos;
        __threadfence();
        s_last = (atomicAdd(&g_done, 1) == BN - 1) ? 1 : 0;
    }
    __syncthreads();
    if (s_last) {
        if (tid < 64) {
            float lv = __ldcg(&g_loss_l[tid]);
            float cv = __ldcg(&g_loss_c[tid]);
            float nv = (float)__ldcg(&g_fn[tid]);
#pragma unroll
            for (int o = 16; o; o >>= 1) {
                lv += __shfl_xor_sync(0xFFFFFFFFu, lv, o);
                cv += __shfl_xor_sync(0xFFFFFFFFu, cv, o);
                nv += __shfl_xor_sync(0xFFFFFFFFu, nv, o);
            }
            if (lane == 0) { s_rf[w] = lv; s_rf[w + 2] = cv; s_rf[w + 4] = nv; }
        }
        __syncthreads();
        if (tid == 0) {
            const float n = fmaxf(s_rf[4] + s_rf[5], 1.0f);
            out[0] = (s_rf[0] + s_rf[1]) / n;
            out[1] = (s_rf[2] + s_rf[3]) / n;
            g_done = 0;   // self-reset
        }
    }
}

extern "C" void kernel_launch(void* const* d_in, const int* in_sizes, int n_in,
                              void* d_out, int out_size) {
    const float* loc = (const float*)d_in[0];
    const float* conf = (const float*)d_in[1];
    const float* priors = (const float*)d_in[2];
    const float* targets = (const float*)d_in[3];
    float* out = (float*)d_out;

    const int post_dyn = IMGB + (L1CAP + L2CAP) * 4;   // 45168 B
    cudaFuncSetAttribute(k_post, cudaFuncAttributeMaxDynamicSharedMemorySize, post_dyn);

    k_big<<<MBLK + CEB, TPB>>>(conf, loc, priors, targets);
    k_post<<<BN, TPK, post_dyn>>>(out);
}

// round 15
// speedup vs baseline: 1.2087x; 1.0005x over previous
#include <cuda_runtime.h>
#include <cstdint>

#define BN 64
#define PP 8732
#define CC 81
#define KT 16
#define NR (BN * PP)
#define TPI 69                 // tiles per image (68 full + 1 of 28 rows)
#define CEB (BN * TPI)         // 4416
#define NCH 16
#define CHUNK 546
#define MBLK (BN * NCH)        // 1024 matchA blocks (first in grid)
#define TPB 128
#define THRESH 0.5f
#define VAR0 0.1f
#define VAR1 0.2f
#define TPK 1024
#define IMGB (PP * 4)
#define NBIN 8192
#define L1CAP 2048
#define L2CAP 512

// ---------------- scratch ----------------
__device__ __align__(16) float g_bto[NR];
__device__ __align__(16) int   g_bti[NR];
__device__ __align__(16) float g_lm[NR];
__device__ int   g_hist[BN * NBIN];              // reset by k_post after use
__device__ unsigned long long g_best[BN * KT];   // idempotent atomicMax accumulator
__device__ float g_acc_l[BN], g_acc_s[BN];       // reset by k_post
__device__ int   g_acc_n[BN];                    // reset by k_post
__device__ int   g_match[BN];                    // reset by k_post
__device__ float g_loss_l[BN], g_loss_c[BN];
__device__ int   g_fn[BN];
__device__ int   g_done;                          // self-resetting

// ---------------- helpers ----------------
static __device__ __forceinline__ unsigned su32(const void* p) {
    return (unsigned)__cvta_generic_to_shared(p);
}
#define MBAR_INIT(a, c) \
    asm volatile("mbarrier.init.shared.b64 [%0], %1;" :: "r"(a), "r"(c) : "memory")
#define MBAR_EXPECT(a, n) \
    asm volatile("mbarrier.arrive.expect_tx.shared.b64 _, [%0], %1;" :: "r"(a), "r"(n) : "memory")
#define BULK_G2S(dst, src, n, mbar) \
    asm volatile("cp.async.bulk.shared::cta.global.mbarrier::complete_tx::bytes [%0], [%1], %2, [%3];" \
                 :: "r"(dst), "l"(src), "r"(n), "r"(mbar) : "memory")
#define MBAR_WAITP(a, par) do {                                                     \
    unsigned _dn = 0;                                                               \
    while (!_dn) {                                                                  \
        asm volatile("{\n\t.reg .pred p;\n\t"                                       \
            "mbarrier.try_wait.parity.acquire.cta.shared::cta.b64 p, [%1], %2, 0x989680;\n\t" \
            "selp.b32 %0, 1, 0, p;\n\t}"                                            \
            : "=r"(_dn) : "r"(a), "r"((unsigned)(par)) : "memory");                 \
    }                                                                               \
} while (0)

static __device__ __forceinline__ int warp_suffix_incl(int v, int lane) {
#pragma unroll
    for (int o = 1; o < 32; o <<= 1) {
        int t = __shfl_down_sync(0xFFFFFFFFu, v, o);
        if (lane + o < 32) v += t;
    }
    return v;
}

// ---------------- smem union for k_big ----------------
struct SmCE {
    float buf[TPI == 69 ? (128 * CC) : 0];   // 41472 B
    float4 tt[KT];
    int   lab[KT];
    int   fp[KT];
    float fov[KT];
    float rf[4], rs[4];
    int   ri[4];
};
struct SmMatch { float4 pr[CHUNK]; float4 tt[KT]; float area[KT]; unsigned long long best[KT]; };
union SmU { SmCE ce; SmMatch ma; };

// ---------------- kernel 1: matchA + fused CE/phase-1 ----------------
__global__ __launch_bounds__(TPB) void k_big(const float* __restrict__ conf,
                                             const float* __restrict__ loc,
                                             const float* __restrict__ priors,
                                             const float* __restrict__ targets) {
    __shared__ __align__(16) SmU sm;
    __shared__ __align__(8) unsigned long long s_mbar;
    const int blk = blockIdx.x;
    const int tid = threadIdx.x;
    const int lane = tid & 31;

    if (blk < MBLK) {
        // ================= matchA role =================
        const int b = blk >> 4;
        const int c = blk & 15;

        if (tid < KT) {
            const float* tg = targets + (size_t)(b * KT + tid) * 6;
            sm.ma.tt[tid] = make_float4(tg[2], tg[3], tg[4], tg[5]);
            sm.ma.area[tid] = (tg[4] - tg[2]) * (tg[5] - tg[3]);
            sm.ma.best[tid] = 0ull;
        }
        const int p0 = c * CHUNK;
        const int np = (p0 + CHUNK <= PP) ? CHUNK : (PP - p0);
        for (int i = tid; i < np; i += TPB)
            sm.ma.pr[i] = ((const float4*)priors)[p0 + i];
        __syncthreads();

        for (int i = tid; i < np; i += TPB) {
            const float4 pr = sm.ma.pr[i];
            const float parea = (pr.z - pr.x) * (pr.w - pr.y);
            float bestov = -1.0f;
            int besti = 0;
#pragma unroll
            for (int k = 0; k < KT; k++) {
                const float4 t = sm.ma.tt[k];
                float ix = fminf(t.z, pr.z) - fmaxf(t.x, pr.x);
                float iy = fminf(t.w, pr.w) - fmaxf(t.y, pr.y);
                float inter = fmaxf(ix, 0.0f) * fmaxf(iy, 0.0f);
                float ov = inter / (sm.ma.area[k] + parea - inter);
                if (ov > bestov) { bestov = ov; besti = k; }
            }
            g_bto[b * PP + p0 + i] = bestov;
            g_bti[b * PP + p0 + i] = besti;
        }

        for (int k = 0; k < KT; k++) {
            const float4 t = sm.ma.tt[k];
            const float ta = sm.ma.area[k];
            unsigned long long key = 0ull;
            for (int i = tid; i < np; i += TPB) {
                const float4 pr = sm.ma.pr[i];
                const float parea = (pr.z - pr.x) * (pr.w - pr.y);
                float ix = fminf(t.z, pr.z) - fmaxf(t.x, pr.x);
                float iy = fminf(t.w, pr.w) - fmaxf(t.y, pr.y);
                float inter = fmaxf(ix, 0.0f) * fmaxf(iy, 0.0f);
                float ov = inter / (ta + parea - inter);
                unsigned long long kk =
                    ((unsigned long long)__float_as_uint(ov) << 32) |
                    (unsigned long long)(0xFFFFFFFFu - (unsigned)(p0 + i));
                if (kk > key) key = kk;
            }
#pragma unroll
            for (int o = 16; o; o >>= 1) {
                unsigned long long other = __shfl_xor_sync(0xFFFFFFFFu, key, o);
                if (other > key) key = other;
            }
            if (lane == 0)
                atomicMax(&sm.ma.best[k], key);
        }
        __syncthreads();
        if (tid < KT)
            atomicMax(&g_best[b * KT + tid], sm.ma.best[tid]);
        __syncthreads();
        if (tid == 0) {
            __threadfence();
            atomicAdd(&g_match[b], 1);          // publish chunk done
        }
    } else {
        // ================= CE + phase-1 role (one image per block) =================
        const int t = blk - MBLK;
        const int b = t / TPI;
        const int ti = t - b * TPI;
        const int r0 = ti * 128;
        const int nv = (r0 + 128 <= PP) ? 128 : (PP - r0);
        const int bPP = b * PP;

        const unsigned mb = su32(&s_mbar);
        if (tid == 0) MBAR_INIT(mb, 1);
        __syncthreads();
        if (tid == 0) {
            MBAR_EXPECT(mb, (unsigned)(nv * CC * 4));
            BULK_G2S(su32(sm.ce.buf), conf + ((size_t)bPP + r0) * CC, (unsigned)(nv * CC * 4), mb);
            // wait for this image's matching to be complete
            while (*(volatile int*)&g_match[b] < NCH) __nanosleep(128);
            __threadfence();
        }
        __syncthreads();
        if (tid < KT) {
            const float* tg = targets + (size_t)(b * KT + tid) * 6;
            sm.ce.lab[tid] = (int)tg[1];
            sm.ce.tt[tid] = make_float4(tg[2], tg[3], tg[4], tg[5]);
            unsigned long long key = g_best[b * KT + tid];
            sm.ce.fp[tid] = (int)(0xFFFFFFFFu - (unsigned)(key & 0xFFFFFFFFull));
            sm.ce.fov[tid] = __uint_as_float((unsigned)(key >> 32));
        }
        __syncthreads();

        // independent global reads before the TMA wait
        const int p = r0 + tid;
        float ov = 0.0f;
        int ki = 0;
        if (tid < nv) {
            ov = g_bto[bPP + p];
            ki = g_bti[bPP + p];
#pragma unroll
            for (int k = 0; k < KT; k++)        // force-assign, last k wins
                if (p == sm.ce.fp[k]) { ov = sm.ce.fov[k]; ki = k; }
        }
        MBAR_WAITP(mb, 0);

        float lmv = 0.0f, spos = 0.0f, lsum = 0.0f;
        int cnt = 0;
        if (tid < nv) {
            const float* row = sm.ce.buf + tid * CC;
            float s0 = 0.0f, s1 = 0.0f, s2 = 0.0f, s3 = 0.0f;
#pragma unroll 5
            for (int i = 0; i + 3 < CC; i += 4) {
                s0 += __expf(row[i]);
                s1 += __expf(row[i + 1]);
                s2 += __expf(row[i + 2]);
                s3 += __expf(row[i + 3]);
            }
            s0 += __expf(row[CC - 1]);
            const float lse = __logf((s0 + s1) + (s2 + s3));
            lmv = lse - row[0];
            const int ct = (ov < THRESH) ? 0 : sm.ce.lab[ki];
            if (ct > 0) {
                cnt = 1;
                spos = lse - row[ct];
                lmv = 0.0f;
                const float4 pr = ((const float4*)priors)[p];
                const float pcx = 0.5f * (pr.x + pr.z), pcy = 0.5f * (pr.y + pr.w);
                const float pw = pr.z - pr.x, ph = pr.w - pr.y;
                const float4 tt = sm.ce.tt[ki];
                float g0 = (0.5f * (tt.x + tt.z) - pcx) / (VAR0 * pw);
                float g1 = (0.5f * (tt.y + tt.w) - pcy) / (VAR0 * ph);
                float g2 = __logf((tt.z - tt.x) / pw) / VAR1;
                float g3 = __logf((tt.w - tt.y) / ph) / VAR1;
                const float4 ld = ((const float4*)loc)[bPP + p];
                float d, ad;
                d = ld.x - g0; ad = fabsf(d); lsum += (ad < 1.0f) ? 0.5f * d * d : ad - 0.5f;
                d = ld.y - g1; ad = fabsf(d); lsum += (ad < 1.0f) ? 0.5f * d * d : ad - 0.5f;
                d = ld.z - g2; ad = fabsf(d); lsum += (ad < 1.0f) ? 0.5f * d * d : ad - 0.5f;
                d = ld.w - g3; ad = fabsf(d); lsum += (ad < 1.0f) ? 0.5f * d * d : ad - 0.5f;
            }
            g_lm[bPP + p] = lmv;
        }

        // warp-aggregated global histogram of lm (positives binned as 0)
        const bool valid = tid < nv;
        const int bin = (int)(__float_as_uint(lmv) >> 19);
        unsigned m = __match_any_sync(0xFFFFFFFFu, bin) &
                     __ballot_sync(0xFFFFFFFFu, valid);
        if (valid && lane == (__ffs(m) - 1))
            atomicAdd(&g_hist[b * NBIN + bin], __popc(m));

        // per-warp accumulate into per-image accumulators
#pragma unroll
        for (int o = 16; o; o >>= 1) {
            spos += __shfl_xor_sync(0xFFFFFFFFu, spos, o);
            lsum += __shfl_xor_sync(0xFFFFFFFFu, lsum, o);
            cnt  += __shfl_xor_sync(0xFFFFFFFFu, cnt, o);
        }
        if (lane == 0 && (tid & ~31) < nv) {
            if (cnt) {
                atomicAdd(&g_acc_n[b], cnt);
                atomicAdd(&g_acc_s[b], spos);
                atomicAdd(&g_acc_l[b], lsum);
            }
        }
    }
}

// ---------------- kernel 2: select + finalize (light) ----------------
// dyn smem: s_lm[PP] | s_list1[L1CAP] | s_list2[L2CAP]
extern __shared__ float psm[];

__global__ __launch_bounds__(TPK) void k_post(float* __restrict__ out) {
    const int b = blockIdx.x;
    const int tid = threadIdx.x;
    const int lane = tid & 31;
    const int w = tid >> 5;

    float* s_lm = psm;
    float* s_list1 = psm + PP;
    float* s_list2 = psm + PP + L1CAP;

    __shared__ int s_wtot[32], s_wsuf[32];
    __shared__ int s_h2[1024];
    __shared__ float s_rf[32];
    __shared__ int s_ri[32];
    __shared__ float s_T;
    __shared__ int s_B, s_rem, s_B2, s_rem2, s_B3, s_rem3;
    __shared__ int s_cnt1, s_cnt2, s_last;
    __shared__ __align__(8) unsigned long long s_mbar;

    const unsigned mb = su32(&s_mbar);
    if (tid == 0) {
        MBAR_INIT(mb, 1);
        MBAR_EXPECT(mb, (unsigned)IMGB);
        BULK_G2S(su32(s_lm), g_lm + b * PP, (unsigned)IMGB, mb);
        s_T = 0.0f; s_cnt1 = 0; s_cnt2 = 0;
    }
    __syncthreads();

    // read per-image accumulators, then reset them
    const int npos = g_acc_n[b];
    const float spos = g_acc_s[b];
    const float lsum = g_acc_l[b];
    if (tid == 0) {
        g_acc_n[b] = 0; g_acc_s[b] = 0.0f; g_acc_l[b] = 0.0f; g_match[b] = 0;
    }

    int k = 3 * npos;
    if (k > PP - 1) k = PP - 1;

    // load + zero this image's histogram, suffix scan to find boundary bin
    int h[8];
    int tot = 0;
    const int base = tid * 8;
    const int hb = b * NBIN;
#pragma unroll
    for (int j = 0; j < 8; j++) {
        h[j] = g_hist[hb + base + j];
        g_hist[hb + base + j] = 0;
        tot += h[j];
    }

    if (k > 0) {
        int sv = warp_suffix_incl(tot, lane);
        if (lane == 0) s_wtot[w] = sv;
        __syncthreads();
        if (tid < 32) {
            int t2 = warp_suffix_incl(s_wtot[tid], tid);
            s_wsuf[tid] = t2 - s_wtot[tid];
        }
        __syncthreads();
        int cumAbove = (sv - tot) + s_wsuf[w];
#pragma unroll
        for (int j = 7; j >= 0; j--) {
            const int c = cumAbove + h[j];
            if (c >= k && cumAbove < k) { s_B = base + j; s_rem = k - cumAbove; }
            cumAbove = c;
        }
        __syncthreads();
        const int B = s_B;

        MBAR_WAITP(mb, 0);

        // pass: sum above B, compact boundary bin
        float sum3 = 0.0f;
        for (int p = tid; p < PP; p += TPK) {
            const float lmv = s_lm[p];
            const int bin = (int)(__float_as_uint(lmv) >> 19);
            if (bin > B) sum3 += lmv;
            else if (bin == B) {
                const int idx = atomicAdd(&s_cnt1, 1);
                if (idx < L1CAP) s_list1[idx] = lmv;
            }
        }
#pragma unroll
        for (int o = 16; o; o >>= 1)
            sum3 += __shfl_xor_sync(0xFFFFFFFFu, sum3, o);
        if (lane == 0) atomicAdd(&s_T, sum3);

        // level A: 10-bit select within list1
        if (tid < 1024) s_h2[tid] = 0;
        __syncthreads();
        const int cnt1 = (s_cnt1 < L1CAP) ? s_cnt1 : L1CAP;
        for (int i = tid; i < cnt1; i += TPK)
            atomicAdd(&s_h2[(__float_as_uint(s_list1[i]) >> 9) & 0x3FF], 1);
        __syncthreads();
        {
            const int totA = s_h2[tid];
            int svA = warp_suffix_incl(totA, lane);
            if (lane == 0) s_wtot[w] = svA;
            __syncthreads();
            if (tid < 32) {
                int t2 = warp_suffix_incl(s_wtot[tid], tid);
                s_wsuf[tid] = t2 - s_wtot[tid];
            }
            __syncthreads();
            const int cumE = (svA - totA) + s_wsuf[w];
            if (cumE + totA >= s_rem && cumE < s_rem) {
                s_B2 = tid;
                s_rem2 = s_rem - cumE;
            }
        }
        __syncthreads();
        const int B2 = s_B2;
        float sumA = 0.0f;
        for (int i = tid; i < cnt1; i += TPK) {
            const float v = s_list1[i];
            const int binA = (int)((__float_as_uint(v) >> 9) & 0x3FF);
            if (binA > B2) sumA += v;
            else if (binA == B2) {
                const int idx = atomicAdd(&s_cnt2, 1);
                if (idx < L2CAP) s_list2[idx] = v;
            }
        }
#pragma unroll
        for (int o = 16; o; o >>= 1)
            sumA += __shfl_xor_sync(0xFFFFFFFFu, sumA, o);
        if (lane == 0 && sumA != 0.0f) atomicAdd(&s_T, sumA);

        // level B: 9-bit select within list2
        if (tid < 512) s_h2[tid] = 0;
        __syncthreads();
        const int cnt2 = (s_cnt2 < L2CAP) ? s_cnt2 : L2CAP;
        for (int i = tid; i < cnt2; i += TPK)
            atomicAdd(&s_h2[__float_as_uint(s_list2[i]) & 0x1FF], 1);
        __syncthreads();
        {
            const int totB = (tid < 512) ? s_h2[tid] : 0;
            int svB = warp_suffix_incl(totB, lane);
            if (lane == 0) s_wtot[w] = svB;
            __syncthreads();
            if (tid < 32) {
                int t2 = warp_suffix_incl(s_wtot[tid], tid);
                s_wsuf[tid] = t2 - s_wtot[tid];
            }
            __syncthreads();
            const int cumE = (svB - totB) + s_wsuf[w];
            if (tid < 512 && cumE + totB >= s_rem2 && cumE < s_rem2) {
                s_B3 = tid;
                s_rem3 = s_rem2 - cumE;
            }
        }
        __syncthreads();
        const int B3 = s_B3;
        float sumB = 0.0f;
        for (int i = tid; i < cnt2; i += TPK) {
            const float v = s_list2[i];
            if ((int)(__float_as_uint(v) & 0x1FF) > B3) sumB += v;
        }
#pragma unroll
        for (int o = 16; o; o >>= 1)
            sumB += __shfl_xor_sync(0xFFFFFFFFu, sumB, o);
        if (lane == 0 && sumB != 0.0f) atomicAdd(&s_T, sumB);
        if (tid == 0) {
            const unsigned bits = ((unsigned)B << 19) | ((unsigned)B2 << 9) | (unsigned)B3;
            s_T += (float)s_rem3 * __uint_as_float(bits);
        }
    } else {
        MBAR_WAITP(mb, 0);   // always drain the TMA before exit
    }
    __syncthreads();

    if (tid == 0) {
        g_loss_l[b] = lsum;
        g_loss_c[b] = spos + s_T;
        g_fn[b] = npos;
        __threadfence();
        s_last = (atomicAdd(&g_done, 1) == BN - 1) ? 1 : 0;
    }
    __syncthreads();
    if (s_last) {
        if (tid < 64) {
            float lv = __ldcg(&g_loss_l[tid]);
            float cv = __ldcg(&g_loss_c[tid]);
            float nv = (float)__ldcg(&g_fn[tid]);
#pragma unroll
            for (int o = 16; o; o >>= 1) {
                lv += __shfl_xor_sync(0xFFFFFFFFu, lv, o);
                cv += __shfl_xor_sync(0xFFFFFFFFu, cv, o);
                nv += __shfl_xor_sync(0xFFFFFFFFu, nv, o);
            }
            if (lane == 0) { s_rf[w] = lv; s_rf[w + 2] = cv; s_rf[w + 4] = nv; }
        }
        __syncthreads();
        if (tid == 0) {
            const float n = fmaxf(s_rf[4] + s_rf[5], 1.0f);
            out[0] = (s_rf[0] + s_rf[1]) / n;
            out[1] = (s_rf[2] + s_rf[3]) / n;
            g_done = 0;   // self-reset
        }
    }
}

extern "C" void kernel_launch(void* const* d_in, const int* in_sizes, int n_in,
                              void* d_out, int out_size) {
    const float* loc = (const float*)d_in[0];
    const float* conf = (const float*)d_in[1];
    const float* priors = (const float*)d_in[2];
    const float* targets = (const float*)d_in[3];
    float* out = (float*)d_out;

    const int post_dyn = IMGB + (L1CAP + L2CAP) * 4;   // 45168 B
    cudaFuncSetAttribute(k_post, cudaFuncAttributeMaxDynamicSharedMemorySize, post_dyn);

    k_big<<<MBLK + CEB, TPB>>>(conf, loc, priors, targets);
    k_post<<<BN, TPK, post_dyn>>>(out);
}